// round 1
// baseline (speedup 1.0000x reference)
#include <cuda_runtime.h>

// Problem constants
#define BB   32
#define TT   512
#define DD   256
#define FF   256
#define MEL  2304
#define EPSV 1e-5f

// Conv tiling
#define BM   64     // rows (b,t positions) per block
#define DKC  8      // input-channel chunk per smem stage

// Intermediate buffers (no allocation allowed; __device__ globals)
__device__ float g_h1[BB * TT * FF];   // 16 MB
__device__ float g_h2[BB * TT * FF];   // 16 MB
__device__ int   g_cum[BB * TT];

// ---------------------------------------------------------------------------
// Fused conv1d(k=3, pad=1) + bias + LayerNorm + ReLU over the F=256 axis.
// GEMM view: M = B*T rows, N = 256, K = 256*3 (im2col). One block computes a
// full 64x256 tile so LayerNorm can be done in-register with warp shuffles
// (each warp's 32 lanes hold the SAME 8 rows, different 8-col groups).
// ---------------------------------------------------------------------------
__global__ __launch_bounds__(256, 2)
void conv_ln_relu(const float* __restrict__ X,    // [B*T, D]
                  const float* __restrict__ W,    // [F, D, 3]
                  const float* __restrict__ bias, // [F]
                  const float* __restrict__ gam,  // [F]
                  const float* __restrict__ bet,  // [F]
                  float* __restrict__ Y)          // [B*T, F]
{
    __shared__ float ws[DKC * 3][FF];      // weights: [d_in_chunk*3 + k][f]
    __shared__ float xs[DKC][BM + 4];      // inputs:  [d_in_chunk][row] (66 used)

    const int tid = threadIdx.x;
    const int tx  = tid & 31;          // 32 col-groups of 8
    const int ty  = tid >> 5;          // 8 row-groups of 8
    const int m0  = blockIdx.x * BM;   // global row of tile (tiles never cross b)
    const int bb  = m0 / TT;
    const int t_base = m0 % TT;

    float acc[8][8];
#pragma unroll
    for (int r = 0; r < 8; r++)
#pragma unroll
        for (int c = 0; c < 8; c++) acc[r][c] = 0.f;

    for (int d0 = 0; d0 < DD; d0 += DKC) {
        __syncthreads();
        // --- stage weights: thread tid == output channel f loads 24 floats
        {
            const float4* wp = (const float4*)(W + (size_t)tid * (DD * 3) + d0 * 3);
#pragma unroll
            for (int i = 0; i < 6; i++) {
                float4 q = wp[i];
                ws[i * 4 + 0][tid] = q.x;
                ws[i * 4 + 1][tid] = q.y;
                ws[i * 4 + 2][tid] = q.z;
                ws[i * 4 + 3][tid] = q.w;
            }
        }
        // --- stage inputs: rows t_base-1 .. t_base+64 (66 rows) x 8 channels
        if (tid < 132) {
            int rr   = tid >> 1;
            int doff = (tid & 1) * 4;
            int t    = t_base + rr - 1;
            float4 v = make_float4(0.f, 0.f, 0.f, 0.f);
            if (t >= 0 && t < TT)
                v = *(const float4*)(X + ((size_t)(bb * TT + t)) * DD + d0 + doff);
            xs[doff + 0][rr] = v.x;
            xs[doff + 1][rr] = v.y;
            xs[doff + 2][rr] = v.z;
            xs[doff + 3][rr] = v.w;
        }
        __syncthreads();

#pragma unroll
        for (int dd = 0; dd < DKC; dd++) {
            float a[10];
            {
                const float* xr = &xs[dd][ty * 8];
                float4 a0 = *(const float4*)(xr);
                float4 a1 = *(const float4*)(xr + 4);
                float2 a2 = *(const float2*)(xr + 8);
                a[0] = a0.x; a[1] = a0.y; a[2] = a0.z; a[3] = a0.w;
                a[4] = a1.x; a[5] = a1.y; a[6] = a1.z; a[7] = a1.w;
                a[8] = a2.x; a[9] = a2.y;
            }
#pragma unroll
            for (int kk = 0; kk < 3; kk++) {
                const float* wr = &ws[dd * 3 + kk][tx * 8];
                float4 b0 = *(const float4*)(wr);
                float4 b1 = *(const float4*)(wr + 4);
                float bv[8] = {b0.x, b0.y, b0.z, b0.w, b1.x, b1.y, b1.z, b1.w};
#pragma unroll
                for (int r = 0; r < 8; r++)
#pragma unroll
                    for (int c = 0; c < 8; c++)
                        acc[r][c] = fmaf(a[r + kk], bv[c], acc[r][c]);
            }
        }
    }

    // --- epilogue: +bias, LayerNorm over F (warp reduction), affine, ReLU
    float gr[8], br[8], bi[8];
    {
        const int C0 = tx * 8;
        float4 g0 = *(const float4*)(gam  + C0), g1 = *(const float4*)(gam  + C0 + 4);
        float4 e0 = *(const float4*)(bet  + C0), e1 = *(const float4*)(bet  + C0 + 4);
        float4 i0 = *(const float4*)(bias + C0), i1 = *(const float4*)(bias + C0 + 4);
        gr[0] = g0.x; gr[1] = g0.y; gr[2] = g0.z; gr[3] = g0.w;
        gr[4] = g1.x; gr[5] = g1.y; gr[6] = g1.z; gr[7] = g1.w;
        br[0] = e0.x; br[1] = e0.y; br[2] = e0.z; br[3] = e0.w;
        br[4] = e1.x; br[5] = e1.y; br[6] = e1.z; br[7] = e1.w;
        bi[0] = i0.x; bi[1] = i0.y; bi[2] = i0.z; bi[3] = i0.w;
        bi[4] = i1.x; bi[5] = i1.y; bi[6] = i1.z; bi[7] = i1.w;
    }

#pragma unroll
    for (int r = 0; r < 8; r++) {
        float s = 0.f, q = 0.f;
#pragma unroll
        for (int c = 0; c < 8; c++) {
            float v = acc[r][c] + bi[c];
            acc[r][c] = v;
            s += v;
            q += v * v;
        }
#pragma unroll
        for (int o = 16; o > 0; o >>= 1) {
            s += __shfl_xor_sync(0xffffffffu, s, o);
            q += __shfl_xor_sync(0xffffffffu, q, o);
        }
        const float mu  = s * (1.f / FF);
        const float var = q * (1.f / FF) - mu * mu;
        const float rs  = rsqrtf(var + EPSV);

        float v[8];
#pragma unroll
        for (int c = 0; c < 8; c++)
            v[c] = fmaxf(fmaf((acc[r][c] - mu) * rs, gr[c], br[c]), 0.f);

        const size_t R = (size_t)(m0 + ty * 8 + r);
        float4* dst = (float4*)(Y + R * FF + tx * 8);
        dst[0] = make_float4(v[0], v[1], v[2], v[3]);
        dst[1] = make_float4(v[4], v[5], v[6], v[7]);
    }
}

// ---------------------------------------------------------------------------
// dur_pred = relu(h2 @ lin_w + lin_b), one warp per (b,t) row.
// ---------------------------------------------------------------------------
__global__ __launch_bounds__(256)
void linear_relu(const float* __restrict__ H, const float* __restrict__ w,
                 const float* __restrict__ b, float* __restrict__ out)
{
    const int warp = threadIdx.x >> 5;
    const int lane = threadIdx.x & 31;
    const int row  = blockIdx.x * 8 + warp;
    const float* h = H + (size_t)row * FF;
    float s = 0.f;
#pragma unroll
    for (int i = 0; i < 8; i++)
        s = fmaf(h[lane + i * 32], w[lane + i * 32], s);
#pragma unroll
    for (int o = 16; o > 0; o >>= 1) s += __shfl_xor_sync(0xffffffffu, s, o);
    if (lane == 0) out[row] = fmaxf(s + b[0], 0.f);
}

// ---------------------------------------------------------------------------
// Inclusive cumsum of target durations, one block per batch.
// ---------------------------------------------------------------------------
__global__ __launch_bounds__(512)
void cumsum_k(const int* __restrict__ target, int* __restrict__ cum)
{
    __shared__ int s[TT];
    const int b = blockIdx.x, tid = threadIdx.x;
    s[tid] = target[b * TT + tid];
    __syncthreads();
#pragma unroll
    for (int off = 1; off < TT; off <<= 1) {
        int v = (tid >= off) ? s[tid - off] : 0;
        __syncthreads();
        s[tid] += v;
        __syncthreads();
    }
    cum[b * TT + tid] = s[tid];
}

// ---------------------------------------------------------------------------
// Length-regulator gather: out[b, t_out, :] = x[b, upper_bound(cum, t_out), :]
// masked by t_out < cum[T-1]. 16 output rows per block, 16 lanes per row.
// ---------------------------------------------------------------------------
__global__ __launch_bounds__(256)
void gather_k(const float* __restrict__ x, const int* __restrict__ cum,
              float* __restrict__ out)
{
    __shared__ int sc[TT];
    const int b   = blockIdx.y;
    const int tid = threadIdx.x;
    sc[tid]       = cum[b * TT + tid];
    sc[tid + 256] = cum[b * TT + tid + 256];
    __syncthreads();

    const int total = sc[TT - 1];
    const int lr    = tid >> 4;           // local row 0..15
    const int ln    = tid & 15;           // lane within row
    const int t_out = blockIdx.x * 16 + lr;

    // upper_bound: first i with sc[i] > t_out
    int lo = 0, hi = TT;
    while (lo < hi) {
        int mid = (lo + hi) >> 1;
        if (sc[mid] > t_out) hi = mid; else lo = mid + 1;
    }
    const int  idx   = min(lo, TT - 1);
    const bool valid = (t_out < total);

    const float4* src = (const float4*)(x + ((size_t)(b * TT + idx)) * DD);
    float4*       dst = (float4*)(out + ((size_t)b * MEL + t_out) * DD);
    const float4  z   = make_float4(0.f, 0.f, 0.f, 0.f);
#pragma unroll
    for (int j = 0; j < 4; j++)
        dst[ln + j * 16] = valid ? src[ln + j * 16] : z;
}

// ---------------------------------------------------------------------------
extern "C" void kernel_launch(void* const* d_in, const int* in_sizes, int n_in,
                              void* d_out, int out_size)
{
    const float* x      = (const float*)d_in[0];
    const int*   target = (const int*)  d_in[1];
    // d_in[2] = mel_max_length (compile-time constant 2304)
    const float* w1 = (const float*)d_in[3];
    const float* b1 = (const float*)d_in[4];
    const float* g1 = (const float*)d_in[5];
    const float* e1 = (const float*)d_in[6];
    const float* w2 = (const float*)d_in[7];
    const float* b2 = (const float*)d_in[8];
    const float* g2 = (const float*)d_in[9];
    const float* e2 = (const float*)d_in[10];
    const float* lw = (const float*)d_in[11];
    const float* lb = (const float*)d_in[12];
    float* out = (float*)d_out;

    float *h1, *h2; int* cum;
    cudaGetSymbolAddress((void**)&h1,  g_h1);
    cudaGetSymbolAddress((void**)&h2,  g_h2);
    cudaGetSymbolAddress((void**)&cum, g_cum);

    // Duration-predictor path
    conv_ln_relu<<<(BB * TT) / BM, 256>>>(x,  w1, b1, g1, e1, h1);
    conv_ln_relu<<<(BB * TT) / BM, 256>>>(h1, w2, b2, g2, e2, h2);
    linear_relu<<<(BB * TT) / 8, 256>>>(h2, lw, lb, out + (size_t)BB * MEL * DD);

    // Length-regulator path
    cumsum_k<<<BB, TT>>>(target, cum);
    gather_k<<<dim3(MEL / 16, BB), 256>>>(x, cum, out);
}

// round 2
// speedup vs baseline: 1.0616x; 1.0616x over previous
#include <cuda_runtime.h>

// Problem constants
#define BB   32
#define TT   512
#define DD   256
#define FF   256
#define MEL  2304
#define EPSV 1e-5f

// Conv tiling
#define BM   64     // rows (b,t positions) per block
#define DKC  8      // input-channel chunk per smem stage

typedef unsigned long long u64;

// Intermediate buffers (no allocation allowed; __device__ globals)
__device__ float g_h1[BB * TT * FF];   // 16 MB
__device__ float g_h2[BB * TT * FF];   // 16 MB
__device__ int   g_cum[BB * TT];

// ---- packed f32x2 helpers (FFMA2: 2 FMAs per issue slot; ptxas never emits
//      this from C++, only via PTX fma.rn.f32x2) --------------------------
__device__ __forceinline__ void ffma2(u64& d, u64 a, u64 b) {
    asm("fma.rn.f32x2 %0, %1, %2, %0;" : "+l"(d) : "l"(a), "l"(b));
}
__device__ __forceinline__ u64 pack2(float x) {
    u64 r;
    asm("mov.b64 %0, {%1, %1};" : "=l"(r) : "f"(x));
    return r;
}
__device__ __forceinline__ float2 unpack2(u64 v) {
    float2 f;
    asm("mov.b64 {%0, %1}, %2;" : "=f"(f.x), "=f"(f.y) : "l"(v));
    return f;
}

// ---------------------------------------------------------------------------
// Fused conv1d(k=3, pad=1) + bias + LayerNorm + ReLU over the F=256 axis.
// GEMM view: M = B*T rows, N = 256, K = 256*3. 64x256 tile per block; each
// thread owns an 8x8 sub-tile held as 8x4 packed f32x2 accumulators.
// Warp lanes hold the SAME 8 rows -> LayerNorm via warp shuffles.
// ---------------------------------------------------------------------------
__global__ __launch_bounds__(256, 2)
void conv_ln_relu(const float* __restrict__ X,    // [B*T, D]
                  const float* __restrict__ W,    // [F, D, 3]
                  const float* __restrict__ bias, // [F]
                  const float* __restrict__ gam,  // [F]
                  const float* __restrict__ bet,  // [F]
                  float* __restrict__ Y)          // [B*T, F]
{
    __shared__ float ws[DKC * 3][FF];      // weights: [d_in_chunk*3 + k][f]
    __shared__ float xs[DKC][BM + 4];      // inputs:  [d_in_chunk][row] (66 used)

    const int tid = threadIdx.x;
    const int tx  = tid & 31;          // 32 col-groups of 8
    const int ty  = tid >> 5;          // 8 row-groups of 8
    const int m0  = blockIdx.x * BM;   // global row of tile (tiles never cross b)
    const int bb  = m0 / TT;
    const int t_base = m0 % TT;

    // acc2[r][j] holds columns (2j, 2j+1) of the thread's 8-col group, packed.
    u64 acc2[8][4];
#pragma unroll
    for (int r = 0; r < 8; r++)
#pragma unroll
        for (int j = 0; j < 4; j++) acc2[r][j] = 0ull;

    for (int d0 = 0; d0 < DD; d0 += DKC) {
        __syncthreads();
        // --- stage weights: thread tid == output channel f loads 24 floats
        {
            const float4* wp = (const float4*)(W + (size_t)tid * (DD * 3) + d0 * 3);
#pragma unroll
            for (int i = 0; i < 6; i++) {
                float4 q = wp[i];
                ws[i * 4 + 0][tid] = q.x;
                ws[i * 4 + 1][tid] = q.y;
                ws[i * 4 + 2][tid] = q.z;
                ws[i * 4 + 3][tid] = q.w;
            }
        }
        // --- stage inputs: rows t_base-1 .. t_base+64 (66 rows) x 8 channels
        if (tid < 132) {
            int rr   = tid >> 1;
            int doff = (tid & 1) * 4;
            int t    = t_base + rr - 1;
            float4 v = make_float4(0.f, 0.f, 0.f, 0.f);
            if (t >= 0 && t < TT)
                v = *(const float4*)(X + ((size_t)(bb * TT + t)) * DD + d0 + doff);
            xs[doff + 0][rr] = v.x;
            xs[doff + 1][rr] = v.y;
            xs[doff + 2][rr] = v.z;
            xs[doff + 3][rr] = v.w;
        }
        __syncthreads();

#pragma unroll
        for (int dd = 0; dd < DKC; dd++) {
            // broadcast-packed a values: rows ty*8-? .. need a[0..9]
            u64 a2[10];
            {
                const float* xr = &xs[dd][ty * 8];
                float4 a0 = *(const float4*)(xr);
                float4 a1 = *(const float4*)(xr + 4);
                float2 ax = *(const float2*)(xr + 8);
                a2[0] = pack2(a0.x); a2[1] = pack2(a0.y);
                a2[2] = pack2(a0.z); a2[3] = pack2(a0.w);
                a2[4] = pack2(a1.x); a2[5] = pack2(a1.y);
                a2[6] = pack2(a1.z); a2[7] = pack2(a1.w);
                a2[8] = pack2(ax.x); a2[9] = pack2(ax.y);
            }
#pragma unroll
            for (int kk = 0; kk < 3; kk++) {
                const u64* wr = (const u64*)&ws[dd * 3 + kk][tx * 8];
                u64 b2[4] = {wr[0], wr[1], wr[2], wr[3]};
#pragma unroll
                for (int r = 0; r < 8; r++)
#pragma unroll
                    for (int j = 0; j < 4; j++)
                        ffma2(acc2[r][j], a2[r + kk], b2[j]);
            }
        }
    }

    // --- epilogue: +bias, LayerNorm over F (warp reduction), affine, ReLU
    float gr[8], br[8], bi[8];
    {
        const int C0 = tx * 8;
        float4 g0 = *(const float4*)(gam  + C0), g1 = *(const float4*)(gam  + C0 + 4);
        float4 e0 = *(const float4*)(bet  + C0), e1 = *(const float4*)(bet  + C0 + 4);
        float4 i0 = *(const float4*)(bias + C0), i1 = *(const float4*)(bias + C0 + 4);
        gr[0] = g0.x; gr[1] = g0.y; gr[2] = g0.z; gr[3] = g0.w;
        gr[4] = g1.x; gr[5] = g1.y; gr[6] = g1.z; gr[7] = g1.w;
        br[0] = e0.x; br[1] = e0.y; br[2] = e0.z; br[3] = e0.w;
        br[4] = e1.x; br[5] = e1.y; br[6] = e1.z; br[7] = e1.w;
        bi[0] = i0.x; bi[1] = i0.y; bi[2] = i0.z; bi[3] = i0.w;
        bi[4] = i1.x; bi[5] = i1.y; bi[6] = i1.z; bi[7] = i1.w;
    }

#pragma unroll
    for (int r = 0; r < 8; r++) {
        float v[8];
#pragma unroll
        for (int j = 0; j < 4; j++) {
            float2 p = unpack2(acc2[r][j]);
            v[2 * j + 0] = p.x + bi[2 * j + 0];
            v[2 * j + 1] = p.y + bi[2 * j + 1];
        }
        float s = 0.f, q = 0.f;
#pragma unroll
        for (int c = 0; c < 8; c++) { s += v[c]; q += v[c] * v[c]; }
#pragma unroll
        for (int o = 16; o > 0; o >>= 1) {
            s += __shfl_xor_sync(0xffffffffu, s, o);
            q += __shfl_xor_sync(0xffffffffu, q, o);
        }
        const float mu  = s * (1.f / FF);
        const float var = q * (1.f / FF) - mu * mu;
        const float rs  = rsqrtf(var + EPSV);

#pragma unroll
        for (int c = 0; c < 8; c++)
            v[c] = fmaxf(fmaf((v[c] - mu) * rs, gr[c], br[c]), 0.f);

        const size_t R = (size_t)(m0 + ty * 8 + r);
        float4* dst = (float4*)(Y + R * FF + tx * 8);
        dst[0] = make_float4(v[0], v[1], v[2], v[3]);
        dst[1] = make_float4(v[4], v[5], v[6], v[7]);
    }
}

// ---------------------------------------------------------------------------
// dur_pred = relu(h2 @ lin_w + lin_b), one warp per (b,t) row.
// ---------------------------------------------------------------------------
__global__ __launch_bounds__(256)
void linear_relu(const float* __restrict__ H, const float* __restrict__ w,
                 const float* __restrict__ b, float* __restrict__ out)
{
    const int warp = threadIdx.x >> 5;
    const int lane = threadIdx.x & 31;
    const int row  = blockIdx.x * 8 + warp;
    const float* h = H + (size_t)row * FF;
    float s = 0.f;
#pragma unroll
    for (int i = 0; i < 8; i++)
        s = fmaf(h[lane + i * 32], w[lane + i * 32], s);
#pragma unroll
    for (int o = 16; o > 0; o >>= 1) s += __shfl_xor_sync(0xffffffffu, s, o);
    if (lane == 0) out[row] = fmaxf(s + b[0], 0.f);
}

// ---------------------------------------------------------------------------
// Inclusive cumsum of target durations, one block per batch.
// ---------------------------------------------------------------------------
__global__ __launch_bounds__(512)
void cumsum_k(const int* __restrict__ target, int* __restrict__ cum)
{
    __shared__ int s[TT];
    const int b = blockIdx.x, tid = threadIdx.x;
    s[tid] = target[b * TT + tid];
    __syncthreads();
#pragma unroll
    for (int off = 1; off < TT; off <<= 1) {
        int v = (tid >= off) ? s[tid - off] : 0;
        __syncthreads();
        s[tid] += v;
        __syncthreads();
    }
    cum[b * TT + tid] = s[tid];
}

// ---------------------------------------------------------------------------
// Length-regulator gather: out[b, t_out, :] = x[b, upper_bound(cum, t_out), :]
// masked by t_out < cum[T-1]. 16 output rows per block, 16 lanes per row.
// ---------------------------------------------------------------------------
__global__ __launch_bounds__(256)
void gather_k(const float* __restrict__ x, const int* __restrict__ cum,
              float* __restrict__ out)
{
    __shared__ int sc[TT];
    const int b   = blockIdx.y;
    const int tid = threadIdx.x;
    sc[tid]       = cum[b * TT + tid];
    sc[tid + 256] = cum[b * TT + tid + 256];
    __syncthreads();

    const int total = sc[TT - 1];
    const int lr    = tid >> 4;           // local row 0..15
    const int ln    = tid & 15;           // lane within row
    const int t_out = blockIdx.x * 16 + lr;

    // upper_bound: first i with sc[i] > t_out
    int lo = 0, hi = TT;
    while (lo < hi) {
        int mid = (lo + hi) >> 1;
        if (sc[mid] > t_out) hi = mid; else lo = mid + 1;
    }
    const int  idx   = min(lo, TT - 1);
    const bool valid = (t_out < total);

    const float4* src = (const float4*)(x + ((size_t)(b * TT + idx)) * DD);
    float4*       dst = (float4*)(out + ((size_t)b * MEL + t_out) * DD);
    const float4  z   = make_float4(0.f, 0.f, 0.f, 0.f);
#pragma unroll
    for (int j = 0; j < 4; j++)
        dst[ln + j * 16] = valid ? src[ln + j * 16] : z;
}

// ---------------------------------------------------------------------------
extern "C" void kernel_launch(void* const* d_in, const int* in_sizes, int n_in,
                              void* d_out, int out_size)
{
    const float* x      = (const float*)d_in[0];
    const int*   target = (const int*)  d_in[1];
    // d_in[2] = mel_max_length (compile-time constant 2304)
    const float* w1 = (const float*)d_in[3];
    const float* b1 = (const float*)d_in[4];
    const float* g1 = (const float*)d_in[5];
    const float* e1 = (const float*)d_in[6];
    const float* w2 = (const float*)d_in[7];
    const float* b2 = (const float*)d_in[8];
    const float* g2 = (const float*)d_in[9];
    const float* e2 = (const float*)d_in[10];
    const float* lw = (const float*)d_in[11];
    const float* lb = (const float*)d_in[12];
    float* out = (float*)d_out;

    float *h1, *h2; int* cum;
    cudaGetSymbolAddress((void**)&h1,  g_h1);
    cudaGetSymbolAddress((void**)&h2,  g_h2);
    cudaGetSymbolAddress((void**)&cum, g_cum);

    // Duration-predictor path
    conv_ln_relu<<<(BB * TT) / BM, 256>>>(x,  w1, b1, g1, e1, h1);
    conv_ln_relu<<<(BB * TT) / BM, 256>>>(h1, w2, b2, g2, e2, h2);
    linear_relu<<<(BB * TT) / 8, 256>>>(h2, lw, lb, out + (size_t)BB * MEL * DD);

    // Length-regulator path
    cumsum_k<<<BB, TT>>>(target, cum);
    gather_k<<<dim3(MEL / 16, BB), 256>>>(x, cum, out);
}

// round 9
// speedup vs baseline: 1.9262x; 1.8145x over previous
#include <cuda_runtime.h>
#include <cuda_bf16.h>
#include <cstdint>

// ---------------------------------------------------------------------------
// Problem constants
// ---------------------------------------------------------------------------
#define BB   32
#define TT   512
#define DD   256
#define FF   256
#define MEL  2304
#define EPSV 1e-5f

// conv-GEMM tiling (mma.sync path, base-target compatible)
#define TM      128                 // M rows per CTA
#define KC      64                  // K elems per chunk (bf16) -> 128B rows
#define NCHUNK  12                  // 3 taps * 4 d-chunks
#define GRID_M  ((BB * TT) / TM)    // 128 CTAs

// SMEM layout (dynamic)
#define OFF_BIAS   0
#define OFF_GAM    1024
#define OFF_BET    2048
#define OFF_STATS  3072                  // 128 x float2(mu, rs)
#define OFF_STAGE  8192
#define A_HI 0
#define A_LO 16384
#define B_HI 32768
#define B_LO 65536
#define STAGE_BYTES 98304
#define OFF_V      OFF_STAGE             // epilogue reuses stage area
#define VSTR       260                   // padded floats per v row
#define V_BYTES    (TM * VSTR * 4)       // 133120
#define SMEM_TOTAL (OFF_STAGE + V_BYTES) // 141312

#define SW128(o)   ((o) ^ (((o) >> 3) & 0x70))

// ---------------------------------------------------------------------------
// Device globals (no allocation allowed)
// ---------------------------------------------------------------------------
__device__ __align__(16) float g_h1[BB * TT * FF];
__device__ __align__(16) float g_h2[BB * TT * FF];
__device__ int g_cum[BB * TT];
__device__ __align__(16) unsigned short g_w1hi[3 * FF * DD], g_w1lo[3 * FF * DD];
__device__ __align__(16) unsigned short g_w2hi[3 * FF * DD], g_w2lo[3 * FF * DD];

// ---------------------------------------------------------------------------
// helpers
// ---------------------------------------------------------------------------
__device__ __forceinline__ uint32_t smem_u32(const void* p) {
    uint32_t a;
    asm("{ .reg .u64 t; cvta.to.shared.u64 t, %1; cvt.u32.u64 %0, t; }" : "=r"(a) : "l"(p));
    return a;
}
__device__ __forceinline__ void ldsm_x4(uint32_t* r, uint32_t addr) {
    asm volatile("ldmatrix.sync.aligned.m8n8.x4.shared.b16 {%0,%1,%2,%3}, [%4];"
                 : "=r"(r[0]), "=r"(r[1]), "=r"(r[2]), "=r"(r[3]) : "r"(addr));
}
__device__ __forceinline__ void ldsm_x2(uint32_t* r, uint32_t addr) {
    asm volatile("ldmatrix.sync.aligned.m8n8.x2.shared.b16 {%0,%1}, [%2];"
                 : "=r"(r[0]), "=r"(r[1]) : "r"(addr));
}
__device__ __forceinline__ void mma_bf16(float* c, const uint32_t* a, const uint32_t* b) {
    asm volatile(
        "mma.sync.aligned.m16n8k16.row.col.f32.bf16.bf16.f32 "
        "{%0,%1,%2,%3}, {%4,%5,%6,%7}, {%8,%9}, {%0,%1,%2,%3};"
        : "+f"(c[0]), "+f"(c[1]), "+f"(c[2]), "+f"(c[3])
        : "r"(a[0]), "r"(a[1]), "r"(a[2]), "r"(a[3]), "r"(b[0]), "r"(b[1]));
}
// pack lo-parts of two floats into one bf16x2 word (lo of a in low half)
__device__ __forceinline__ uint32_t lo_pack(float a, float b) {
    float ta = __uint_as_float(__float_as_uint(a) & 0xFFFF0000u);
    float tb = __uint_as_float(__float_as_uint(b) & 0xFFFF0000u);
    float la = a - ta, lb = b - tb;
    uint32_t w;
    asm("cvt.rn.bf16x2.f32 %0, %1, %2;" : "=r"(w) : "f"(lb), "f"(la));
    return w;
}

// ---------------------------------------------------------------------------
// Weight preconversion: hi/lo bf16, layout [kk][f][d]
// ---------------------------------------------------------------------------
__global__ void wsplit_k(const float* __restrict__ w,
                         unsigned short* __restrict__ hi,
                         unsigned short* __restrict__ lo)
{
    int e = blockIdx.x * 256 + threadIdx.x;
    if (e >= 3 * FF * DD) return;
    int kk = e >> 16;
    int f  = (e >> 8) & 255;
    int d  = e & 255;
    float v = w[(f * DD + d) * 3 + kk];
    uint32_t b = __float_as_uint(v);
    hi[e] = (unsigned short)(b >> 16);
    float lv = v - __uint_as_float(b & 0xFFFF0000u);
    unsigned short ls;
    asm("cvt.rn.bf16.f32 %0, %1;" : "=h"(ls) : "f"(lv));
    lo[e] = ls;
}

// ---------------------------------------------------------------------------
// Fused conv1d(k=3,pad=1)+bias+LayerNorm+ReLU via mma.sync split-bf16 GEMM.
// CTA: 128x256 tile. 8 warps in 2(m) x 4(n) -> 64x64 warp tiles.
// ---------------------------------------------------------------------------
__global__ __launch_bounds__(256, 1)
void conv_tc(const float* __restrict__ X,           // [B*T, D] f32
             const unsigned short* __restrict__ WH, // [3][F][D] bf16-hi bits
             const unsigned short* __restrict__ WL, // [3][F][D] bf16-lo bits
             const float* __restrict__ bias,
             const float* __restrict__ gam,
             const float* __restrict__ bet,
             float* __restrict__ Y)                 // [B*T, F] f32
{
    extern __shared__ char sm[];
    const uint32_t smb = smem_u32(sm);
    const int tid  = threadIdx.x;
    const int wid  = tid >> 5;
    const int lane = tid & 31;
    const int m0   = blockIdx.x * TM;
    const int bb   = m0 / TT;
    const int t_base = m0 % TT;

    const int wm = (wid & 1) * 64;   // warp row base
    const int wn = (wid >> 1) * 64;  // warp col base

    // stage LN params / bias
    ((float*)(sm + OFF_BIAS))[tid] = bias[tid];
    ((float*)(sm + OFF_GAM))[tid]  = gam[tid];
    ((float*)(sm + OFF_BET))[tid]  = bet[tid];

    float acc[4][8][4];
#pragma unroll
    for (int i = 0; i < 4; i++)
#pragma unroll
        for (int j = 0; j < 8; j++)
#pragma unroll
            for (int q = 0; q < 4; q++) acc[i][j][q] = 0.f;

    const int ar = tid >> 1, ah = tid & 1;    // A staging: row, col-half
    const int l7  = lane & 7;
    const int lm8 = (lane >> 3) & 1;
    const int lk  = (lane >> 4) & 1;

    for (int ci = 0; ci < NCHUNK; ci++) {
        const int kk = ci >> 2;
        const int d0 = (ci & 3) * KC;
        __syncthreads();   // previous chunk's reads complete (covers param stage on ci=0)

        // ---- stage A (x rows shifted by kk-1, split hi/lo, SW128) ----
        {
            const int t_src = t_base + ar + kk - 1;
            const bool ok = (t_src >= 0) && (t_src < TT);
            const float4* src = (const float4*)(X + ((size_t)(bb * TT + t_src)) * DD + d0 + ah * 32);
            const uint32_t rowoff = (uint32_t)(ar * 128 + ah * 64);
            const float4 z4 = make_float4(0.f, 0.f, 0.f, 0.f);
#pragma unroll
            for (int i = 0; i < 4; i++) {
                float4 f0 = ok ? src[2 * i]     : z4;
                float4 f1 = ok ? src[2 * i + 1] : z4;
                uint4 hq, lq;
                hq.x = __byte_perm(__float_as_uint(f0.x), __float_as_uint(f0.y), 0x7632);
                hq.y = __byte_perm(__float_as_uint(f0.z), __float_as_uint(f0.w), 0x7632);
                hq.z = __byte_perm(__float_as_uint(f1.x), __float_as_uint(f1.y), 0x7632);
                hq.w = __byte_perm(__float_as_uint(f1.z), __float_as_uint(f1.w), 0x7632);
                lq.x = lo_pack(f0.x, f0.y);
                lq.y = lo_pack(f0.z, f0.w);
                lq.z = lo_pack(f1.x, f1.y);
                lq.w = lo_pack(f1.z, f1.w);
                const uint32_t sw = SW128(rowoff + i * 16);
                *(uint4*)(sm + OFF_STAGE + A_HI + sw) = hq;
                *(uint4*)(sm + OFF_STAGE + A_LO + sw) = lq;
            }
        }
        // ---- stage B (preconverted weights, row f = tid) ----
        {
            const uint4* bh = (const uint4*)(WH + ((size_t)(kk * FF + tid)) * DD + d0);
            const uint4* bl = (const uint4*)(WL + ((size_t)(kk * FF + tid)) * DD + d0);
            const uint32_t rowoff = (uint32_t)(tid * 128);
#pragma unroll
            for (int j = 0; j < 8; j++) {
                const uint32_t sw = SW128(rowoff + j * 16);
                *(uint4*)(sm + OFF_STAGE + B_HI + sw) = bh[j];
                *(uint4*)(sm + OFF_STAGE + B_LO + sw) = bl[j];
            }
        }
        __syncthreads();

        // ---- compute: 4 k16-steps, 3 split products ----
#pragma unroll
        for (int ks = 0; ks < 4; ks++) {
            const int kb = ks * 32;
            uint32_t ahi[4][4], alo[4][4];
#pragma unroll
            for (int i = 0; i < 4; i++) {
                const uint32_t off = (uint32_t)((wm + i * 16 + lm8 * 8 + l7) * 128 + kb + lk * 16);
                const uint32_t adr = smb + OFF_STAGE + SW128(off);
                ldsm_x4(ahi[i], adr + A_HI);
                ldsm_x4(alo[i], adr + A_LO);
            }
#pragma unroll
            for (int j = 0; j < 8; j++) {
                const uint32_t boff = (uint32_t)((wn + j * 8 + l7) * 128 + kb + lm8 * 16);
                const uint32_t badr = smb + OFF_STAGE + SW128(boff);
                uint32_t bh[2], bl[2];
                ldsm_x2(bh, badr + B_HI);
                ldsm_x2(bl, badr + B_LO);
#pragma unroll
                for (int i = 0; i < 4; i++) {
                    mma_bf16(acc[i][j], ahi[i], bh);
                    mma_bf16(acc[i][j], ahi[i], bl);
                    mma_bf16(acc[i][j], alo[i], bh);
                }
            }
        }
    }

    // ---- epilogue: acc (+bias) -> V smem ----
    __syncthreads();
    {
        const float* sbias = (const float*)(sm + OFF_BIAS);
        float* V = (float*)(sm + OFF_V);
        const int rq = lane >> 2, cq = (lane & 3) * 2;
#pragma unroll
        for (int i = 0; i < 4; i++) {
            const int r0 = wm + i * 16 + rq;
#pragma unroll
            for (int j = 0; j < 8; j++) {
                const int c = wn + j * 8 + cq;
                const float b0 = sbias[c], b1 = sbias[c + 1];
                *(float2*)(V + (size_t)r0 * VSTR + c) =
                    make_float2(acc[i][j][0] + b0, acc[i][j][1] + b1);
                *(float2*)(V + (size_t)(r0 + 8) * VSTR + c) =
                    make_float2(acc[i][j][2] + b0, acc[i][j][3] + b1);
            }
        }
    }
    __syncthreads();

    // ---- phase A: per-row mean/rstd ----
    if (wid < 4) {
        const int row = wid * 32 + lane;
        const float4* vr = (const float4*)((const float*)(sm + OFF_V) + (size_t)row * VSTR);
        float sum = 0.f, sq = 0.f;
#pragma unroll 8
        for (int q = 0; q < 64; q++) {
            float4 v = vr[q];
            sum += v.x + v.y + v.z + v.w;
            sq  += v.x * v.x + v.y * v.y + v.z * v.z + v.w * v.w;
        }
        const float mu  = sum * (1.f / FF);
        const float var = sq * (1.f / FF) - mu * mu;
        const float rs  = rsqrtf(var + EPSV);
        ((float2*)(sm + OFF_STATS))[row] = make_float2(mu, rs);
    }
    __syncthreads();

    // ---- phase B: LN affine + ReLU, coalesced store ----
    {
        const int rsub = tid >> 6;        // 0..3
        const int cq   = tid & 63;        // float4 column index
        const float4 g = ((const float4*)(sm + OFF_GAM))[cq];
        const float4 e = ((const float4*)(sm + OFF_BET))[cq];
#pragma unroll 4
        for (int it = 0; it < 32; it++) {
            const int r = it * 4 + rsub;
            const float4 v = *(const float4*)((const float*)(sm + OFF_V) + (size_t)r * VSTR + cq * 4);
            const float2 ms = ((const float2*)(sm + OFF_STATS))[r];
            float4 y;
            y.x = fmaxf(fmaf((v.x - ms.x) * ms.y, g.x, e.x), 0.f);
            y.y = fmaxf(fmaf((v.y - ms.x) * ms.y, g.y, e.y), 0.f);
            y.z = fmaxf(fmaf((v.z - ms.x) * ms.y, g.z, e.z), 0.f);
            y.w = fmaxf(fmaf((v.w - ms.x) * ms.y, g.w, e.w), 0.f);
            *(float4*)(Y + ((size_t)(m0 + r)) * FF + cq * 4) = y;
        }
    }
}

// ---------------------------------------------------------------------------
// dur_pred = relu(h2 @ lin_w + lin_b), one warp per (b,t) row.
// ---------------------------------------------------------------------------
__global__ __launch_bounds__(256)
void linear_relu(const float* __restrict__ H, const float* __restrict__ w,
                 const float* __restrict__ b, float* __restrict__ out)
{
    const int warp = threadIdx.x >> 5;
    const int lane = threadIdx.x & 31;
    const int row  = blockIdx.x * 8 + warp;
    const float* h = H + (size_t)row * FF;
    float s = 0.f;
#pragma unroll
    for (int i = 0; i < 8; i++)
        s = fmaf(h[lane + i * 32], w[lane + i * 32], s);
#pragma unroll
    for (int o = 16; o > 0; o >>= 1) s += __shfl_xor_sync(0xffffffffu, s, o);
    if (lane == 0) out[row] = fmaxf(s + b[0], 0.f);
}

// ---------------------------------------------------------------------------
// Inclusive cumsum of target durations, one block per batch.
// ---------------------------------------------------------------------------
__global__ __launch_bounds__(512)
void cumsum_k(const int* __restrict__ target, int* __restrict__ cum)
{
    __shared__ int s[TT];
    const int b = blockIdx.x, tid = threadIdx.x;
    s[tid] = target[b * TT + tid];
    __syncthreads();
#pragma unroll
    for (int off = 1; off < TT; off <<= 1) {
        int v = (tid >= off) ? s[tid - off] : 0;
        __syncthreads();
        s[tid] += v;
        __syncthreads();
    }
    cum[b * TT + tid] = s[tid];
}

// ---------------------------------------------------------------------------
// Length-regulator gather.
// ---------------------------------------------------------------------------
__global__ __launch_bounds__(256)
void gather_k(const float* __restrict__ x, const int* __restrict__ cum,
              float* __restrict__ out)
{
    __shared__ int sc[TT];
    const int b   = blockIdx.y;
    const int tid = threadIdx.x;
    sc[tid]       = cum[b * TT + tid];
    sc[tid + 256] = cum[b * TT + tid + 256];
    __syncthreads();

    const int total = sc[TT - 1];
    const int lr    = tid >> 4;
    const int ln    = tid & 15;
    const int t_out = blockIdx.x * 16 + lr;

    int lo = 0, hi = TT;
    while (lo < hi) {
        int mid = (lo + hi) >> 1;
        if (sc[mid] > t_out) hi = mid; else lo = mid + 1;
    }
    const int  idx   = min(lo, TT - 1);
    const bool valid = (t_out < total);

    const float4* src = (const float4*)(x + ((size_t)(b * TT + idx)) * DD);
    float4*       dst = (float4*)(out + ((size_t)b * MEL + t_out) * DD);
    const float4  z   = make_float4(0.f, 0.f, 0.f, 0.f);
#pragma unroll
    for (int j = 0; j < 4; j++)
        dst[ln + j * 16] = valid ? src[ln + j * 16] : z;
}

// ---------------------------------------------------------------------------
extern "C" void kernel_launch(void* const* d_in, const int* in_sizes, int n_in,
                              void* d_out, int out_size)
{
    const float* x      = (const float*)d_in[0];
    const int*   target = (const int*)  d_in[1];
    const float* w1 = (const float*)d_in[3];
    const float* b1 = (const float*)d_in[4];
    const float* g1 = (const float*)d_in[5];
    const float* e1 = (const float*)d_in[6];
    const float* w2 = (const float*)d_in[7];
    const float* b2 = (const float*)d_in[8];
    const float* g2 = (const float*)d_in[9];
    const float* e2 = (const float*)d_in[10];
    const float* lw = (const float*)d_in[11];
    const float* lb = (const float*)d_in[12];
    float* out = (float*)d_out;

    float *h1, *h2; int* cum;
    unsigned short *w1h, *w1l, *w2h, *w2l;
    cudaGetSymbolAddress((void**)&h1,  g_h1);
    cudaGetSymbolAddress((void**)&h2,  g_h2);
    cudaGetSymbolAddress((void**)&cum, g_cum);
    cudaGetSymbolAddress((void**)&w1h, g_w1hi);
    cudaGetSymbolAddress((void**)&w1l, g_w1lo);
    cudaGetSymbolAddress((void**)&w2h, g_w2hi);
    cudaGetSymbolAddress((void**)&w2l, g_w2lo);

    cudaFuncSetAttribute(conv_tc, cudaFuncAttributeMaxDynamicSharedMemorySize, SMEM_TOTAL);

    // weight preconversion (trivial cost)
    wsplit_k<<<768, 256>>>(w1, w1h, w1l);
    wsplit_k<<<768, 256>>>(w2, w2h, w2l);

    // length-regulator path (independent)
    cumsum_k<<<BB, TT>>>(target, cum);
    gather_k<<<dim3(MEL / 16, BB), 256>>>(x, cum, out);

    // duration-predictor path
    conv_tc<<<GRID_M, 256, SMEM_TOTAL>>>(x,  w1h, w1l, b1, g1, e1, h1);
    conv_tc<<<GRID_M, 256, SMEM_TOTAL>>>(h1, w2h, w2l, b2, g2, e2, h2);
    linear_relu<<<(BB * TT) / 8, 256>>>(h2, lw, lb, out + (size_t)BB * MEL * DD);
}